// round 3
// baseline (speedup 1.0000x reference)
#include <cuda_runtime.h>
#include <math.h>

// Problem constants
#define BB    256
#define NOISE 100
#define RANKV 512
#define R4    128
#define R2    256

typedef unsigned long long u64;

// ---------------- scratch (device globals, no alloc) ----------------
__device__ __align__(16) float g_noiseT[NOISE * BB];            // [k][b]
__device__ __align__(16) float g_latentT[256 * BB];             // [ci][b]
__device__ __align__(16) float g_t1[2][R4 * 16 * BB];           // [stack][(ci*16+l)*B + b]
__device__ __align__(16) float g_t2[2][R2 * 31 * BB];           // [stack][(ci*31+l)*B + b]
__device__ __align__(16) float g_s3[2][BB * RANKV * 32];        // [stack][b*16384 + r*32 + t]
__device__ __align__(16) float g_a[BB * RANKV * 3];             // [b*1536 + r*3 + ch]  (c * coef)

// ---------------- f32x2 helpers ----------------
__device__ __forceinline__ u64 pk2(float lo, float hi) {
    u64 r; asm("mov.b64 %0, {%1,%2};" : "=l"(r) : "f"(lo), "f"(hi)); return r;
}
__device__ __forceinline__ void upk2(u64 v, float &lo, float &hi) {
    asm("mov.b64 {%0,%1}, %2;" : "=f"(lo), "=f"(hi) : "l"(v));
}
__device__ __forceinline__ void fma2(u64 &d, u64 a, u64 b) {
    asm("fma.rn.f32x2 %0, %1, %2, %0;" : "+l"(d) : "l"(a), "l"(b));
}

// ---------------- block-wide (sum, sumsq) reduction -------------
__device__ __forceinline__ void blk_stats(float &s, float &q, float *red) {
    #pragma unroll
    for (int o = 16; o; o >>= 1) {
        s += __shfl_down_sync(0xffffffffu, s, o);
        q += __shfl_down_sync(0xffffffffu, q, o);
    }
    int tid = threadIdx.x, w = tid >> 5;
    if ((tid & 31) == 0) { red[w] = s; red[16 + w] = q; }
    __syncthreads();
    if (tid == 0) {
        int nw = blockDim.x >> 5;
        float S = 0.f, Q = 0.f;
        for (int i = 0; i < nw; i++) { S += red[i]; Q += red[16 + i]; }
        red[0] = S; red[16] = Q;
    }
    __syncthreads();
    s = red[0]; q = red[16];
    __syncthreads();
}

// ---------------- K0: transpose noise -> [k][b] ----------------
__global__ void k0_transpose(const float *__restrict__ noise) {
    int k = blockIdx.x, b = threadIdx.x;
    g_noiseT[k * BB + b] = noise[b * NOISE + k];
}

// ---------------- K1: z = noise@W^T+b, BN, lrelu(0.01); emb -> latentT ----------------
__global__ __launch_bounds__(256) void k1_latent(
    const float *__restrict__ lin_w, const float *__restrict__ lin_b,
    const float *__restrict__ bn0_g, const float *__restrict__ bn0_b,
    const float *__restrict__ emb, const int *__restrict__ label) {
    int ch = blockIdx.x, b = threadIdx.x;
    if (ch < 128) {
        __shared__ float ws[NOISE];
        __shared__ float red[32];
        if (b < NOISE) ws[b] = lin_w[ch * NOISE + b];
        __syncthreads();
        float acc = lin_b[ch];
        #pragma unroll 4
        for (int k = 0; k < NOISE; k++) acc += g_noiseT[k * BB + b] * ws[k];
        float s = acc, q = acc * acc;
        blk_stats(s, q, red);
        float m = s * (1.0f / BB);
        float v = q * (1.0f / BB) - m * m;
        float sc = rsqrtf(v + 1e-5f) * bn0_g[ch];
        float y = (acc - m) * sc + bn0_b[ch];
        y = (y >= 0.f) ? y : 0.01f * y;
        g_latentT[ch * BB + b] = y;
    } else {
        int j = ch - 128;
        g_latentT[ch * BB + b] = emb[label[b] * 128 + j];
    }
}

// ---------------- K2: c branch (convT k=3 on L=1) + BN + lrelu(0.2), * coef ----------------
// 4 output channels per block to cut latent re-reads 4x.
__global__ __launch_bounds__(256) void k2_cbranch(
    const float *__restrict__ c_w1, const float *__restrict__ c_b1,
    const float *__restrict__ c_g1, const float *__restrict__ c_be1,
    const float *__restrict__ coef) {
    int r0 = blockIdx.x * 4, b = threadIdx.x;
    __shared__ float ws[4 * 768];
    __shared__ float red[32];
    for (int i = b; i < 4 * 768; i += 256) {
        int rl = i / 768, rem = i % 768;
        int ci = rem / 3, kk = rem % 3;
        ws[i] = c_w1[(ci * RANKV + (r0 + rl)) * 3 + kk];
    }
    __syncthreads();
    float acc[4][3];
    #pragma unroll
    for (int rl = 0; rl < 4; rl++) {
        float bias = c_b1[r0 + rl];
        acc[rl][0] = bias; acc[rl][1] = bias; acc[rl][2] = bias;
    }
    for (int ci = 0; ci < 256; ci++) {
        float x = g_latentT[ci * BB + b];
        #pragma unroll
        for (int rl = 0; rl < 4; rl++) {
            const float *wp = &ws[rl * 768 + ci * 3];
            acc[rl][0] += x * wp[0];
            acc[rl][1] += x * wp[1];
            acc[rl][2] += x * wp[2];
        }
    }
    const float invN = 1.0f / (BB * 3);
    #pragma unroll
    for (int rl = 0; rl < 4; rl++) {
        float s = acc[rl][0] + acc[rl][1] + acc[rl][2];
        float q = acc[rl][0] * acc[rl][0] + acc[rl][1] * acc[rl][1] + acc[rl][2] * acc[rl][2];
        blk_stats(s, q, red);
        float m = s * invN, v = q * invN - m * m;
        int r = r0 + rl;
        float sc = rsqrtf(v + 1e-5f) * c_g1[r];
        float sh = c_be1[r];
        float cf = coef[r];
        float *dst = &g_a[b * (RANKV * 3) + r * 3];
        #pragma unroll
        for (int ch = 0; ch < 3; ch++) {
            float y = (acc[rl][ch] - m) * sc + sh;
            y = (y >= 0.f) ? y : 0.2f * y;
            dst[ch] = y * cf;
        }
    }
}

// ---------------- K3: layer1 (GEMM 256 -> co x 16) + BN + lrelu(0.2) ----------------
__global__ __launch_bounds__(256) void k3_layer1(
    const float *__restrict__ hw1, const float *__restrict__ hb1,
    const float *__restrict__ hg1, const float *__restrict__ hbe1,
    const float *__restrict__ ww1, const float *__restrict__ wb1,
    const float *__restrict__ wg1, const float *__restrict__ wbe1) {
    int co = blockIdx.x, st = blockIdx.y, b = threadIdx.x;
    const float *W  = st ? ww1  : hw1;
    const float *Bi = st ? wb1  : hb1;
    const float *G  = st ? wg1  : hg1;
    const float *Be = st ? wbe1 : hbe1;

    __shared__ __align__(16) float ws[256 * 16];   // 16 KB
    __shared__ float red[32];
    for (int i = b; i < 256 * 16; i += 256) {
        int ci = i >> 4, l = i & 15;
        ws[i] = W[(ci * R4 + co) * 16 + l];
    }
    __syncthreads();

    float bias = Bi[co];
    float acc[16];
    #pragma unroll
    for (int l = 0; l < 16; l++) acc[l] = bias;

    for (int ci = 0; ci < 256; ci++) {
        float x = g_latentT[ci * BB + b];
        const float4 *w4 = (const float4 *)&ws[ci * 16];
        #pragma unroll
        for (int j = 0; j < 4; j++) {
            float4 w = w4[j];
            acc[4 * j + 0] += x * w.x;
            acc[4 * j + 1] += x * w.y;
            acc[4 * j + 2] += x * w.z;
            acc[4 * j + 3] += x * w.w;
        }
    }
    float s = 0.f, q = 0.f;
    #pragma unroll
    for (int l = 0; l < 16; l++) { s += acc[l]; q += acc[l] * acc[l]; }
    blk_stats(s, q, red);
    const float invN = 1.0f / (BB * 16);
    float m = s * invN, v = q * invN - m * m;
    float sc = rsqrtf(v + 1e-5f) * G[co];
    float sh = Be[co];
    float *T1 = g_t1[st];
    #pragma unroll
    for (int l = 0; l < 16; l++) {
        float y = (acc[l] - m) * sc + sh;
        y = (y >= 0.f) ? y : 0.2f * y;
        T1[(co * 16 + l) * BB + b] = y;
    }
}

// ---------------- K4: layer2 convT k=16 (16 -> 31) + BN + lrelu(0.2), f32x2 ------
// Block: 256 threads = 2 co x 128 b-pairs (full batch). Each thread holds ALL 31
// t-outputs for one co (acc[31] u64) -> every (l,k) pair valid, zero predication
// waste, 16 FMA2 per 8B load. 256 thr/block -> 255-reg cap (no spill risk).
__global__ __launch_bounds__(256) void k4_layer2(
    const float *__restrict__ hw2, const float *__restrict__ hb2,
    const float *__restrict__ hg2, const float *__restrict__ hbe2,
    const float *__restrict__ ww2, const float *__restrict__ wb2,
    const float *__restrict__ wg2, const float *__restrict__ wbe2) {
    int cot = blockIdx.x;                 // 0..127 -> 2 co each
    int st  = blockIdx.y;
    const float *W  = st ? ww2  : hw2;
    const float *Bi = st ? wb2  : hb2;
    const float *G  = st ? wg2  : hg2;
    const float *Be = st ? wbe2 : hbe2;

    int tid   = threadIdx.x;
    int bpair = tid & 127;
    int col   = tid >> 7;                 // 0..1
    int b     = bpair * 2;
    int co    = cot * 2 + col;

    __shared__ __align__(16) float ws[128 * 2 * 16];   // [ci][col][k] 16 KB
    __shared__ float sred[8][2];
    __shared__ float bnp[2][2];

    for (int i = tid; i < 4096; i += 256) {
        int ci = i >> 5, rem = i & 31;
        int cl = rem >> 4, k = rem & 15;
        ws[i] = W[(ci * R2 + cot * 2 + cl) * 16 + k];
    }
    __syncthreads();

    float bias = Bi[co];
    u64 acc[31];
    u64 bias2 = pk2(bias, bias);
    #pragma unroll
    for (int t = 0; t < 31; t++) acc[t] = bias2;

    const float *X = g_t1[st] + b;
    for (int ci = 0; ci < R4; ci++) {
        u64 xv[16];
        const float *xb = X + ci * 16 * BB;
        #pragma unroll
        for (int l = 0; l < 16; l++) xv[l] = *(const u64 *)&xb[l * BB];
        const float *wrow = &ws[ci * 32 + col * 16];
        #pragma unroll
        for (int k = 0; k < 16; k++) {
            float w = wrow[k];                // warp-uniform LDS (broadcast)
            u64 wk = pk2(w, w);
            #pragma unroll
            for (int l = 0; l < 16; l++) fma2(acc[k + l], xv[l], wk);
        }
    }

    // BN stats per co over (31 t x 256 b). co group = 4 warps.
    float s = 0.f, q = 0.f;
    #pragma unroll
    for (int t = 0; t < 31; t++) {
        float a, c; upk2(acc[t], a, c);
        s += a + c; q += a * a + c * c;
    }
    #pragma unroll
    for (int o = 16; o; o >>= 1) {
        s += __shfl_down_sync(0xffffffffu, s, o);
        q += __shfl_down_sync(0xffffffffu, q, o);
    }
    int wid = tid >> 5;
    if ((tid & 31) == 0) { sred[wid][0] = s; sred[wid][1] = q; }
    __syncthreads();
    if (tid < 2) {
        float S = 0.f, Q = 0.f;
        for (int w = tid * 4; w < tid * 4 + 4; w++) { S += sred[w][0]; Q += sred[w][1]; }
        const float invN = 1.0f / (BB * 31);
        float m = S * invN, v = Q * invN - m * m;
        int c = cot * 2 + tid;
        float sc = rsqrtf(v + 1e-5f) * G[c];
        bnp[tid][0] = sc;
        bnp[tid][1] = Be[c] - m * sc;
    }
    __syncthreads();

    float sc = bnp[col][0], sh = bnp[col][1];
    float *T2 = g_t2[st] + b;
    #pragma unroll
    for (int t = 0; t < 31; t++) {
        float a, c; upk2(acc[t], a, c);
        float y0 = a * sc + sh; y0 = (y0 >= 0.f) ? y0 : 0.2f * y0;
        float y1 = c * sc + sh; y1 = (y1 >= 0.f) ? y1 : 0.2f * y1;
        *(u64 *)&T2[(co * 31 + t) * BB] = pk2(y0, y1);
    }
}

// ---------------- K5: layer3 convT k=2 (31 -> 32) + tanh, f32x2 -----------------
// 256 threads = 8 r-groups (2 r each) x 2 t-halves x 16 b-pairs. Rolling-x inner
// loop: 2 loads feed 8 FMA2. Per-thread r-blocking of 2 halves x-traffic.
__global__ __launch_bounds__(256) void k5_layer3(
    const float *__restrict__ hw3, const float *__restrict__ hb3,
    const float *__restrict__ ww3, const float *__restrict__ wb3) {
    int rt = blockIdx.x;   // 0..31 (16 r each)
    int bt = blockIdx.y;   // 0..7  (32 b each)
    int st = blockIdx.z;
    const float *W  = st ? ww3 : hw3;
    const float *Bi = st ? wb3 : hb3;

    int tid   = threadIdx.x;
    int bl    = tid & 15;
    int thalf = (tid >> 4) & 1;
    int rg    = tid >> 5;              // 0..7
    int b     = bt * 32 + bl * 2;
    int r0    = (rt * 8 + rg) * 2;     // thread handles r0, r0+1

    float bias0 = Bi[r0], bias1 = Bi[r0 + 1];
    u64 acc[2][16];
    #pragma unroll
    for (int j = 0; j < 16; j++) { acc[0][j] = pk2(bias0, bias0); acc[1][j] = pk2(bias1, bias1); }

    const float *X = g_t2[st] + b;
    const int l0 = thalf * 16;

    for (int ci = 0; ci < R2; ci++) {
        // 4 weights (r0,k0) (r0,k1) (r1,k0) (r1,k1) contiguous; warp-uniform load.
        float4 wv = *(const float4 *)&W[(ci * RANKV + r0) * 2];
        u64 w0a = pk2(wv.x, wv.x), w1a = pk2(wv.y, wv.y);
        u64 w0b = pk2(wv.z, wv.z), w1b = pk2(wv.w, wv.w);
        const float *xb = X + ci * 31 * BB;
        if (thalf == 0) {
            u64 xprev = 0ull;   // x[-1]
            #pragma unroll
            for (int j = 0; j < 16; j++) {
                u64 xcur = *(const u64 *)&xb[j * BB];           // l = j
                fma2(acc[0][j], xcur, w0a); fma2(acc[0][j], xprev, w1a);
                fma2(acc[1][j], xcur, w0b); fma2(acc[1][j], xprev, w1b);
                xprev = xcur;
            }
        } else {
            u64 xprev = *(const u64 *)&xb[15 * BB];             // l = 15
            #pragma unroll
            for (int j = 0; j < 15; j++) {
                u64 xcur = *(const u64 *)&xb[(16 + j) * BB];    // l = 16+j
                fma2(acc[0][j], xcur, w0a); fma2(acc[0][j], xprev, w1a);
                fma2(acc[1][j], xcur, w0b); fma2(acc[1][j], xprev, w1b);
                xprev = xcur;
            }
            // j = 15 (t = 31): x[31] doesn't exist -> only k=1 term
            fma2(acc[0][15], xprev, w1a);
            fma2(acc[1][15], xprev, w1b);
        }
    }

    // tanh + store: per (b lane, r) 16 consecutive t floats = 4 float4 stores
    float *S = g_s3[st];
    #pragma unroll
    for (int cl = 0; cl < 2; cl++) {
        float o0[16], o1[16];
        #pragma unroll
        for (int j = 0; j < 16; j++) {
            float a, c;
            upk2(acc[cl][j], a, c);
            o0[j] = tanhf(a);
            o1[j] = tanhf(c);
        }
        float *p0 = &S[(u64)b * (RANKV * 32) + (r0 + cl) * 32 + l0];
        float *p1 = p0 + (RANKV * 32);
        #pragma unroll
        for (int j4 = 0; j4 < 4; j4++) {
            ((float4 *)p0)[j4] = make_float4(o0[4 * j4], o0[4 * j4 + 1], o0[4 * j4 + 2], o0[4 * j4 + 3]);
            ((float4 *)p1)[j4] = make_float4(o1[4 * j4], o1[4 * j4 + 1], o1[4 * j4 + 2], o1[4 * j4 + 3]);
        }
    }
}

// ---------------- K6: out[b,ch,y,x] = sum_r a[b,r,ch] h[b,r,y] w[b,r,x] ----------------
__global__ __launch_bounds__(256) void k6_final(float *__restrict__ out) {
    int b = blockIdx.x, tid = threadIdx.x;
    __shared__ float aS[RANKV * 3];       // 6 KB
    __shared__ float hS[32 * 33];         // padded
    __shared__ float wS[32 * 33];

    const float *A = &g_a[b * (RANKV * 3)];
    for (int i = tid; i < RANKV * 3; i += 256) aS[i] = A[i];

    const float *H  = &g_s3[0][(u64)b * (RANKV * 32)];
    const float *Wt = &g_s3[1][(u64)b * (RANKV * 32)];

    int x = tid & 31, yb = tid >> 5;    // yb in 0..7
    float acc[4][3];
    #pragma unroll
    for (int yi = 0; yi < 4; yi++)
        #pragma unroll
        for (int ch = 0; ch < 3; ch++) acc[yi][ch] = 0.f;

    for (int r0 = 0; r0 < RANKV; r0 += 32) {
        __syncthreads();
        for (int i = tid; i < 1024; i += 256) {
            int rr = i >> 5, t = i & 31;
            hS[rr * 33 + t] = H[(r0 + rr) * 32 + t];
            wS[rr * 33 + t] = Wt[(r0 + rr) * 32 + t];
        }
        __syncthreads();
        #pragma unroll 4
        for (int rr = 0; rr < 32; rr++) {
            float wv = wS[rr * 33 + x];
            const float *ap = &aS[(r0 + rr) * 3];
            float a0 = ap[0], a1 = ap[1], a2 = ap[2];
            #pragma unroll
            for (int yi = 0; yi < 4; yi++) {
                float hv = hS[rr * 33 + yb + 8 * yi];
                float p = hv * wv;
                acc[yi][0] += p * a0;
                acc[yi][1] += p * a1;
                acc[yi][2] += p * a2;
            }
        }
    }
    #pragma unroll
    for (int yi = 0; yi < 4; yi++) {
        int y = yb + 8 * yi;
        #pragma unroll
        for (int ch = 0; ch < 3; ch++)
            out[((b * 3 + ch) * 32 + y) * 32 + x] = acc[yi][ch];
    }
}

// ---------------- launch ----------------
extern "C" void kernel_launch(void* const* d_in, const int* in_sizes, int n_in,
                              void* d_out, int out_size) {
    const float *noise = (const float *)d_in[0];
    const int   *label = (const int *)d_in[1];
    const float *lin_w = (const float *)d_in[2];
    const float *lin_b = (const float *)d_in[3];
    const float *bn0_g = (const float *)d_in[4];
    const float *bn0_b = (const float *)d_in[5];
    const float *emb   = (const float *)d_in[6];
    const float *c_w1  = (const float *)d_in[7];
    const float *c_b1  = (const float *)d_in[8];
    const float *c_g1  = (const float *)d_in[9];
    const float *c_be1 = (const float *)d_in[10];
    const float *h_w1  = (const float *)d_in[11];
    const float *h_b1  = (const float *)d_in[12];
    const float *h_g1  = (const float *)d_in[13];
    const float *h_be1 = (const float *)d_in[14];
    const float *h_w2  = (const float *)d_in[15];
    const float *h_b2  = (const float *)d_in[16];
    const float *h_g2  = (const float *)d_in[17];
    const float *h_be2 = (const float *)d_in[18];
    const float *h_w3  = (const float *)d_in[19];
    const float *h_b3  = (const float *)d_in[20];
    const float *w_w1  = (const float *)d_in[21];
    const float *w_b1  = (const float *)d_in[22];
    const float *w_g1  = (const float *)d_in[23];
    const float *w_be1 = (const float *)d_in[24];
    const float *w_w2  = (const float *)d_in[25];
    const float *w_b2  = (const float *)d_in[26];
    const float *w_g2  = (const float *)d_in[27];
    const float *w_be2 = (const float *)d_in[28];
    const float *w_w3  = (const float *)d_in[29];
    const float *w_b3  = (const float *)d_in[30];
    const float *coef  = (const float *)d_in[31];

    k0_transpose<<<NOISE, BB>>>(noise);
    k1_latent<<<256, BB>>>(lin_w, lin_b, bn0_g, bn0_b, emb, label);
    k2_cbranch<<<RANKV / 4, BB>>>(c_w1, c_b1, c_g1, c_be1, coef);
    k3_layer1<<<dim3(R4, 2), 256>>>(h_w1, h_b1, h_g1, h_be1,
                                    w_w1, w_b1, w_g1, w_be1);
    k4_layer2<<<dim3(R4, 2), 256>>>(h_w2, h_b2, h_g2, h_be2,
                                    w_w2, w_b2, w_g2, w_be2);
    k5_layer3<<<dim3(32, 8, 2), 256>>>(h_w3, h_b3, w_w3, w_b3);
    k6_final<<<BB, 256>>>((float *)d_out);
}

// round 5
// speedup vs baseline: 2.2597x; 2.2597x over previous
#include <cuda_runtime.h>
#include <math.h>

// Problem constants
#define BB    256
#define NOISE 100
#define RANKV 512
#define R4    128
#define R2    256

typedef unsigned long long u64;

// ---------------- scratch (device globals, no alloc) ----------------
__device__ __align__(16) float g_noiseT[NOISE * BB];            // [k][b]
__device__ __align__(16) float g_latentT[256 * BB];             // [ci][b]
__device__ __align__(16) float g_t1[2][R4 * 16 * BB];           // [stack][(ci*16+l)*B + b]
__device__ __align__(16) float g_t2[2][R2 * 31 * BB];           // [stack][(ci*31+l)*B + b]
__device__ __align__(16) float g_s3[2][BB * RANKV * 32];        // [stack][b*16384 + r*32 + t]
__device__ __align__(16) float g_a[BB * RANKV * 3];             // [b*1536 + r*3 + ch]  (c * coef)

// ---------------- f32x2 helpers ----------------
__device__ __forceinline__ u64 pk2(float lo, float hi) {
    u64 r; asm("mov.b64 %0, {%1,%2};" : "=l"(r) : "f"(lo), "f"(hi)); return r;
}
__device__ __forceinline__ void upk2(u64 v, float &lo, float &hi) {
    asm("mov.b64 {%0,%1}, %2;" : "=f"(lo), "=f"(hi) : "l"(v));
}
__device__ __forceinline__ void fma2(u64 &d, u64 a, u64 b) {
    asm("fma.rn.f32x2 %0, %1, %2, %0;" : "+l"(d) : "l"(a), "l"(b));
}

// ---------------- block-wide (sum, sumsq) reduction -------------
__device__ __forceinline__ void blk_stats(float &s, float &q, float *red) {
    #pragma unroll
    for (int o = 16; o; o >>= 1) {
        s += __shfl_down_sync(0xffffffffu, s, o);
        q += __shfl_down_sync(0xffffffffu, q, o);
    }
    int tid = threadIdx.x, w = tid >> 5;
    if ((tid & 31) == 0) { red[w] = s; red[16 + w] = q; }
    __syncthreads();
    if (tid == 0) {
        int nw = blockDim.x >> 5;
        float S = 0.f, Q = 0.f;
        for (int i = 0; i < nw; i++) { S += red[i]; Q += red[16 + i]; }
        red[0] = S; red[16] = Q;
    }
    __syncthreads();
    s = red[0]; q = red[16];
    __syncthreads();
}

// ---------------- K0: transpose noise -> [k][b] ----------------
__global__ void k0_transpose(const float *__restrict__ noise) {
    int k = blockIdx.x, b = threadIdx.x;
    g_noiseT[k * BB + b] = noise[b * NOISE + k];
}

// ---------------- K1: z = noise@W^T+b, BN, lrelu(0.01); emb -> latentT ----------------
__global__ __launch_bounds__(256) void k1_latent(
    const float *__restrict__ lin_w, const float *__restrict__ lin_b,
    const float *__restrict__ bn0_g, const float *__restrict__ bn0_b,
    const float *__restrict__ emb, const int *__restrict__ label) {
    int ch = blockIdx.x, b = threadIdx.x;
    if (ch < 128) {
        __shared__ float ws[NOISE];
        __shared__ float red[32];
        if (b < NOISE) ws[b] = lin_w[ch * NOISE + b];
        __syncthreads();
        float acc = lin_b[ch];
        #pragma unroll 4
        for (int k = 0; k < NOISE; k++) acc += g_noiseT[k * BB + b] * ws[k];
        float s = acc, q = acc * acc;
        blk_stats(s, q, red);
        float m = s * (1.0f / BB);
        float v = q * (1.0f / BB) - m * m;
        float sc = rsqrtf(v + 1e-5f) * bn0_g[ch];
        float y = (acc - m) * sc + bn0_b[ch];
        y = (y >= 0.f) ? y : 0.01f * y;
        g_latentT[ch * BB + b] = y;
    } else {
        int j = ch - 128;
        g_latentT[ch * BB + b] = emb[label[b] * 128 + j];
    }
}

// ---------------- K2: c branch (convT k=3 on L=1) + BN + lrelu(0.2), * coef ----------------
__global__ __launch_bounds__(256) void k2_cbranch(
    const float *__restrict__ c_w1, const float *__restrict__ c_b1,
    const float *__restrict__ c_g1, const float *__restrict__ c_be1,
    const float *__restrict__ coef) {
    int r0 = blockIdx.x * 4, b = threadIdx.x;
    __shared__ float ws[4 * 768];
    __shared__ float red[32];
    for (int i = b; i < 4 * 768; i += 256) {
        int rl = i / 768, rem = i % 768;
        int ci = rem / 3, kk = rem % 3;
        ws[i] = c_w1[(ci * RANKV + (r0 + rl)) * 3 + kk];
    }
    __syncthreads();
    float acc[4][3];
    #pragma unroll
    for (int rl = 0; rl < 4; rl++) {
        float bias = c_b1[r0 + rl];
        acc[rl][0] = bias; acc[rl][1] = bias; acc[rl][2] = bias;
    }
    for (int ci = 0; ci < 256; ci++) {
        float x = g_latentT[ci * BB + b];
        #pragma unroll
        for (int rl = 0; rl < 4; rl++) {
            const float *wp = &ws[rl * 768 + ci * 3];
            acc[rl][0] += x * wp[0];
            acc[rl][1] += x * wp[1];
            acc[rl][2] += x * wp[2];
        }
    }
    const float invN = 1.0f / (BB * 3);
    #pragma unroll
    for (int rl = 0; rl < 4; rl++) {
        float s = acc[rl][0] + acc[rl][1] + acc[rl][2];
        float q = acc[rl][0] * acc[rl][0] + acc[rl][1] * acc[rl][1] + acc[rl][2] * acc[rl][2];
        blk_stats(s, q, red);
        float m = s * invN, v = q * invN - m * m;
        int r = r0 + rl;
        float sc = rsqrtf(v + 1e-5f) * c_g1[r];
        float sh = c_be1[r];
        float cf = coef[r];
        float *dst = &g_a[b * (RANKV * 3) + r * 3];
        #pragma unroll
        for (int ch = 0; ch < 3; ch++) {
            float y = (acc[rl][ch] - m) * sc + sh;
            y = (y >= 0.f) ? y : 0.2f * y;
            dst[ch] = y * cf;
        }
    }
}

// ---------------- K3: layer1 (GEMM 256 -> co x 16) + BN + lrelu(0.2), f32x2 ------
// 256 threads = 128 b-pairs x 2 l-halves (8 l each). acc[8] u64 -> low regs, high ILP.
__global__ __launch_bounds__(256) void k3_layer1(
    const float *__restrict__ hw1, const float *__restrict__ hb1,
    const float *__restrict__ hg1, const float *__restrict__ hbe1,
    const float *__restrict__ ww1, const float *__restrict__ wb1,
    const float *__restrict__ wg1, const float *__restrict__ wbe1) {
    int co = blockIdx.x, st = blockIdx.y;
    const float *W  = st ? ww1  : hw1;
    const float *Bi = st ? wb1  : hb1;
    const float *G  = st ? wg1  : hg1;
    const float *Be = st ? wbe1 : hbe1;

    int tid   = threadIdx.x;
    int bpair = tid & 127;
    int lh    = tid >> 7;          // 0..1 -> l in [lh*8, lh*8+8)
    int b     = bpair * 2;

    __shared__ __align__(16) float ws[256 * 16];   // 16 KB
    __shared__ float red[32];
    __shared__ float bnp[2];
    for (int i = tid; i < 256 * 16; i += 256) {
        int ci = i >> 4, l = i & 15;
        ws[i] = W[(ci * R4 + co) * 16 + l];
    }
    __syncthreads();

    float bias = Bi[co];
    u64 acc[8];
    #pragma unroll
    for (int j = 0; j < 8; j++) acc[j] = pk2(bias, bias);

    const float *X = g_latentT + b;
    #pragma unroll 4
    for (int ci = 0; ci < 256; ci++) {
        u64 x = *(const u64 *)&X[ci * BB];
        const float4 *w4 = (const float4 *)&ws[ci * 16 + lh * 8];
        float4 wa = w4[0], wb = w4[1];
        fma2(acc[0], x, pk2(wa.x, wa.x));
        fma2(acc[1], x, pk2(wa.y, wa.y));
        fma2(acc[2], x, pk2(wa.z, wa.z));
        fma2(acc[3], x, pk2(wa.w, wa.w));
        fma2(acc[4], x, pk2(wb.x, wb.x));
        fma2(acc[5], x, pk2(wb.y, wb.y));
        fma2(acc[6], x, pk2(wb.z, wb.z));
        fma2(acc[7], x, pk2(wb.w, wb.w));
    }

    float s = 0.f, q = 0.f;
    #pragma unroll
    for (int j = 0; j < 8; j++) {
        float a, c; upk2(acc[j], a, c);
        s += a + c; q += a * a + c * c;
    }
    blk_stats(s, q, red);
    if (tid == 0) {
        const float invN = 1.0f / (BB * 16);
        float m = s * invN, v = q * invN - m * m;
        float sc = rsqrtf(v + 1e-5f) * G[co];
        bnp[0] = sc;
        bnp[1] = Be[co] - m * sc;
    }
    __syncthreads();
    float sc = bnp[0], sh = bnp[1];
    float *T1 = g_t1[st] + b;
    #pragma unroll
    for (int j = 0; j < 8; j++) {
        float a, c; upk2(acc[j], a, c);
        float y0 = a * sc + sh; y0 = (y0 >= 0.f) ? y0 : 0.2f * y0;
        float y1 = c * sc + sh; y1 = (y1 >= 0.f) ? y1 : 0.2f * y1;
        *(u64 *)&T1[(co * 16 + lh * 8 + j) * BB] = pk2(y0, y1);
    }
}

// ---------------- K4: layer2 convT k=16 (16 -> 31) + BN + lrelu(0.2), f32x2 ------
// t-PARITY SPLIT: 256 threads = 128 b-pairs x 2 parities. Even-t threads take all
// (l,k) with l+k even (16 accs), odd-t the rest (15). Every pair used exactly once.
// Per-ci x loads split into two 8-element phases -> live set ~100 regs, no spill
// at the __launch_bounds__(256,2) 128-reg cap.
__global__ __launch_bounds__(256, 2) void k4_layer2(
    const float *__restrict__ hw2, const float *__restrict__ hb2,
    const float *__restrict__ hg2, const float *__restrict__ hbe2,
    const float *__restrict__ ww2, const float *__restrict__ wb2,
    const float *__restrict__ wg2, const float *__restrict__ wbe2) {
    int co = blockIdx.x;                  // 0..255
    int st = blockIdx.y;
    const float *W  = st ? ww2  : hw2;
    const float *Bi = st ? wb2  : hb2;
    const float *G  = st ? wg2  : hg2;
    const float *Be = st ? wbe2 : hbe2;

    int tid   = threadIdx.x;
    int bpair = tid & 127;
    int par   = tid >> 7;                 // parity of t this thread produces
    int b     = bpair * 2;

    __shared__ __align__(16) float ws[128 * 16];   // [ci][k] 8 KB
    __shared__ float red[32];
    __shared__ float bnp[2];

    for (int i = tid; i < 2048; i += 256) {
        int ci = i >> 4, k = i & 15;
        ws[i] = W[(ci * R2 + co) * 16 + k];
    }
    __syncthreads();

    float bias = Bi[co];
    u64 acc[16];
    u64 bias2 = pk2(bias, bias);
    #pragma unroll
    for (int j = 0; j < 16; j++) acc[j] = bias2;

    const float *X = g_t1[st] + b;
    for (int ci = 0; ci < R4; ci++) {
        const float *xb = X + ci * 16 * BB;
        const float *wr = &ws[ci * 16];
        u64 wk[16];
        #pragma unroll
        for (int k = 0; k < 16; k++) { float w = wr[k]; wk[k] = pk2(w, w); }
        #pragma unroll
        for (int ph = 0; ph < 2; ph++) {       // two 8-l phases: bounded live xv
            u64 xv[8];
            #pragma unroll
            for (int j = 0; j < 8; j++) xv[j] = *(const u64 *)&xb[(ph * 8 + j) * BB];
            if (par == 0) {
                #pragma unroll
                for (int j = 0; j < 8; j++) {
                    const int l = ph * 8 + j;
                    #pragma unroll
                    for (int kk = 0; kk < 8; kk++) {
                        const int k = (l & 1) + 2 * kk;   // l+k even
                        fma2(acc[(l + k) >> 1], xv[j], wk[k]);
                    }
                }
            } else {
                #pragma unroll
                for (int j = 0; j < 8; j++) {
                    const int l = ph * 8 + j;
                    #pragma unroll
                    for (int kk = 0; kk < 8; kk++) {
                        const int k = ((l & 1) ^ 1) + 2 * kk;  // l+k odd
                        fma2(acc[(l + k) >> 1], xv[j], wk[k]);
                    }
                }
            }
        }
    }

    // BN stats over (31 t x 256 b); parity-1 has only 15 valid accs.
    int tn = 16 - par;
    float s = 0.f, q = 0.f;
    #pragma unroll
    for (int j = 0; j < 16; j++) {
        if (j < tn) {
            float a, c; upk2(acc[j], a, c);
            s += a + c; q += a * a + c * c;
        }
    }
    blk_stats(s, q, red);
    if (tid == 0) {
        const float invN = 1.0f / (BB * 31);
        float m = s * invN, v = q * invN - m * m;
        float sc = rsqrtf(v + 1e-5f) * G[co];
        bnp[0] = sc;
        bnp[1] = Be[co] - m * sc;
    }
    __syncthreads();

    float sc = bnp[0], sh = bnp[1];
    float *T2 = g_t2[st] + b;
    #pragma unroll
    for (int j = 0; j < 16; j++) {
        if (j < tn) {
            int t = 2 * j + par;
            float a, c; upk2(acc[j], a, c);
            float y0 = a * sc + sh; y0 = (y0 >= 0.f) ? y0 : 0.2f * y0;
            float y1 = c * sc + sh; y1 = (y1 >= 0.f) ? y1 : 0.2f * y1;
            *(u64 *)&T2[(co * 31 + t) * BB] = pk2(y0, y1);
        }
    }
}

// ---------------- K5: layer3 convT k=2 (31 -> 32) + tanh, f32x2 -----------------
// 256 threads = 16 b-pairs x 4 t-quarters x 4 r-groups; thread owns 4 r x 8 t x 2 b.
// 4-r blocking: 64 FMA2 per 9 loads. acc[4][8] u64; xv[9] rolling window (MLP 9).
__global__ __launch_bounds__(256, 2) void k5_layer3(
    const float *__restrict__ hw3, const float *__restrict__ hb3,
    const float *__restrict__ ww3, const float *__restrict__ wb3) {
    int rt = blockIdx.x;   // 0..31 (16 r each)
    int bt = blockIdx.y;   // 0..7  (32 b each)
    int st = blockIdx.z;
    const float *W  = st ? ww3 : hw3;
    const float *Bi = st ? wb3 : hb3;

    int tid = threadIdx.x;
    int bl  = tid & 15;
    int tq  = (tid >> 4) & 3;
    int rg  = tid >> 6;                 // 0..3
    int b   = bt * 32 + bl * 2;
    int r0  = rt * 16 + rg * 4;         // thread handles r0..r0+3
    int t0  = tq * 8;                   // thread handles t0..t0+7

    u64 acc[4][8];
    #pragma unroll
    for (int rr = 0; rr < 4; rr++) {
        float bias = Bi[r0 + rr];
        u64 b2 = pk2(bias, bias);
        #pragma unroll
        for (int j = 0; j < 8; j++) acc[rr][j] = b2;
    }

    const float *X = g_t2[st] + b;
    for (int ci = 0; ci < R2; ci++) {
        const float *wp = &W[(ci * RANKV + r0) * 2];   // warp-uniform
        float4 wv0 = *(const float4 *)wp;
        float4 wv1 = *(const float4 *)(wp + 4);
        u64 wk0[4], wk1[4];
        wk0[0] = pk2(wv0.x, wv0.x); wk1[0] = pk2(wv0.y, wv0.y);
        wk0[1] = pk2(wv0.z, wv0.z); wk1[1] = pk2(wv0.w, wv0.w);
        wk0[2] = pk2(wv1.x, wv1.x); wk1[2] = pk2(wv1.y, wv1.y);
        wk0[3] = pk2(wv1.z, wv1.z); wk1[3] = pk2(wv1.w, wv1.w);

        const float *xb = X + ci * 31 * BB;
        u64 xv[9];  // xv[0] = x[t0-1] (0 if t0==0); xv[1+j] = x[t0+j] (0 if ==31)
        xv[0] = (t0 == 0) ? 0ull : *(const u64 *)&xb[(t0 - 1) * BB];
        #pragma unroll
        for (int j = 0; j < 7; j++) xv[1 + j] = *(const u64 *)&xb[(t0 + j) * BB];
        xv[8] = (t0 + 7 < 31) ? *(const u64 *)&xb[(t0 + 7) * BB] : 0ull;

        #pragma unroll
        for (int j = 0; j < 8; j++) {
            #pragma unroll
            for (int rr = 0; rr < 4; rr++) {
                fma2(acc[rr][j], xv[1 + j], wk0[rr]);   // k=0 term: x[t]
                fma2(acc[rr][j], xv[j],     wk1[rr]);   // k=1 term: x[t-1]
            }
        }
    }

    float *S = g_s3[st];
    #pragma unroll
    for (int rr = 0; rr < 4; rr++) {
        float o0[8], o1[8];
        #pragma unroll
        for (int j = 0; j < 8; j++) {
            float a, c; upk2(acc[rr][j], a, c);
            o0[j] = tanhf(a);
            o1[j] = tanhf(c);
        }
        float *p0 = &S[(u64)b * (RANKV * 32) + (r0 + rr) * 32 + t0];
        float *p1 = p0 + (RANKV * 32);
        ((float4 *)p0)[0] = make_float4(o0[0], o0[1], o0[2], o0[3]);
        ((float4 *)p0)[1] = make_float4(o0[4], o0[5], o0[6], o0[7]);
        ((float4 *)p1)[0] = make_float4(o1[0], o1[1], o1[2], o1[3]);
        ((float4 *)p1)[1] = make_float4(o1[4], o1[5], o1[6], o1[7]);
    }
}

// ---------------- K6: out[b,ch,y,x] = sum_r a[b,r,ch] h[b,r,y] w[b,r,x] ----------------
__global__ __launch_bounds__(256) void k6_final(float *__restrict__ out) {
    int b = blockIdx.x, tid = threadIdx.x;
    __shared__ float aS[RANKV * 3];       // 6 KB
    __shared__ float hS[32 * 33];         // padded
    __shared__ float wS[32 * 33];

    const float *A = &g_a[b * (RANKV * 3)];
    for (int i = tid; i < RANKV * 3; i += 256) aS[i] = A[i];

    const float *H  = &g_s3[0][(u64)b * (RANKV * 32)];
    const float *Wt = &g_s3[1][(u64)b * (RANKV * 32)];

    int x = tid & 31, yb = tid >> 5;    // yb in 0..7
    float acc[4][3];
    #pragma unroll
    for (int yi = 0; yi < 4; yi++)
        #pragma unroll
        for (int ch = 0; ch < 3; ch++) acc[yi][ch] = 0.f;

    for (int r0 = 0; r0 < RANKV; r0 += 32) {
        __syncthreads();
        for (int i = tid; i < 1024; i += 256) {
            int rr = i >> 5, t = i & 31;
            hS[rr * 33 + t] = H[(r0 + rr) * 32 + t];
            wS[rr * 33 + t] = Wt[(r0 + rr) * 32 + t];
        }
        __syncthreads();
        #pragma unroll 4
        for (int rr = 0; rr < 32; rr++) {
            float wv = wS[rr * 33 + x];
            const float *ap = &aS[(r0 + rr) * 3];
            float a0 = ap[0], a1 = ap[1], a2 = ap[2];
            #pragma unroll
            for (int yi = 0; yi < 4; yi++) {
                float hv = hS[rr * 33 + yb + 8 * yi];
                float p = hv * wv;
                acc[yi][0] += p * a0;
                acc[yi][1] += p * a1;
                acc[yi][2] += p * a2;
            }
        }
    }
    #pragma unroll
    for (int yi = 0; yi < 4; yi++) {
        int y = yb + 8 * yi;
        #pragma unroll
        for (int ch = 0; ch < 3; ch++)
            out[((b * 3 + ch) * 32 + y) * 32 + x] = acc[yi][ch];
    }
}

// ---------------- launch ----------------
extern "C" void kernel_launch(void* const* d_in, const int* in_sizes, int n_in,
                              void* d_out, int out_size) {
    const float *noise = (const float *)d_in[0];
    const int   *label = (const int *)d_in[1];
    const float *lin_w = (const float *)d_in[2];
    const float *lin_b = (const float *)d_in[3];
    const float *bn0_g = (const float *)d_in[4];
    const float *bn0_b = (const float *)d_in[5];
    const float *emb   = (const float *)d_in[6];
    const float *c_w1  = (const float *)d_in[7];
    const float *c_b1  = (const float *)d_in[8];
    const float *c_g1  = (const float *)d_in[9];
    const float *c_be1 = (const float *)d_in[10];
    const float *h_w1  = (const float *)d_in[11];
    const float *h_b1  = (const float *)d_in[12];
    const float *h_g1  = (const float *)d_in[13];
    const float *h_be1 = (const float *)d_in[14];
    const float *h_w2  = (const float *)d_in[15];
    const float *h_b2  = (const float *)d_in[16];
    const float *h_g2  = (const float *)d_in[17];
    const float *h_be2 = (const float *)d_in[18];
    const float *h_w3  = (const float *)d_in[19];
    const float *h_b3  = (const float *)d_in[20];
    const float *w_w1  = (const float *)d_in[21];
    const float *w_b1  = (const float *)d_in[22];
    const float *w_g1  = (const float *)d_in[23];
    const float *w_be1 = (const float *)d_in[24];
    const float *w_w2  = (const float *)d_in[25];
    const float *w_b2  = (const float *)d_in[26];
    const float *w_g2  = (const float *)d_in[27];
    const float *w_be2 = (const float *)d_in[28];
    const float *w_w3  = (const float *)d_in[29];
    const float *w_b3  = (const float *)d_in[30];
    const float *coef  = (const float *)d_in[31];

    k0_transpose<<<NOISE, BB>>>(noise);
    k1_latent<<<256, BB>>>(lin_w, lin_b, bn0_g, bn0_b, emb, label);
    k2_cbranch<<<RANKV / 4, BB>>>(c_w1, c_b1, c_g1, c_be1, coef);
    k3_layer1<<<dim3(R4, 2), 256>>>(h_w1, h_b1, h_g1, h_be1,
                                    w_w1, w_b1, w_g1, w_be1);
    k4_layer2<<<dim3(R2, 2), 256>>>(h_w2, h_b2, h_g2, h_be2,
                                    w_w2, w_b2, w_g2, w_be2);
    k5_layer3<<<dim3(32, 8, 2), 256>>>(h_w3, h_b3, w_w3, w_b3);
    k6_final<<<BB, 256>>>((float *)d_out);
}